// round 1
// baseline (speedup 1.0000x reference)
#include <cuda_runtime.h>
#include <math.h>

#define NB 16
#define NN 48
#define HID 64
#define MSG 64
#define EDGE 16
#define NL 128
#define TGT 128
#define NE (NB*NN*NN)    // 36864 edges
#define NNODE (NB*NN)    // 768 nodes

// -------- device scratch (static; no allocation) --------
__device__ float d_S[4*NL*MSG];     // prefix sums of msg_w2 over h' at cuts 16/32/48/64: [sel][c][m]
__device__ float d_Bv[4*MSG];       // prefix sums of msg_b2: [sel][m]
__device__ float d_r2[NE*NL];       // relu2 activations per edge [e'][c]
__device__ float d_hf[NNODE*HID];   // h_first
__device__ float d_hA[NNODE*HID];
__device__ float d_hB[NNODE*HID];
__device__ float d_mask[NNODE];
__device__ float d_tmp[NNODE*TGT];

// -------- prep: prefix-sum weight matrices --------
__global__ void prep_kernel(const float* __restrict__ w2, const float* __restrict__ b2) {
    int c = blockIdx.x;   // 0..127
    int m = threadIdx.x;  // 0..63
    const float* p = w2 + c*4096 + m*64;
    float acc = 0.f, s16 = 0.f, s32 = 0.f, s48 = 0.f;
    #pragma unroll
    for (int h = 0; h < 64; ++h) {
        acc += p[h];
        if (h == 15) s16 = acc;
        if (h == 31) s32 = acc;
        if (h == 47) s48 = acc;
    }
    d_S[0*8192 + c*64 + m] = s16;
    d_S[1*8192 + c*64 + m] = s32;
    d_S[2*8192 + c*64 + m] = s48;
    d_S[3*8192 + c*64 + m] = acc;
    if (c == 0) {
        const float* q = b2 + m*64;
        float a = 0.f, t16 = 0.f, t32 = 0.f, t48 = 0.f;
        for (int h = 0; h < 64; ++h) {
            a += q[h];
            if (h == 15) t16 = a;
            if (h == 31) t32 = a;
            if (h == 47) t48 = a;
        }
        d_Bv[0*64+m] = t16; d_Bv[1*64+m] = t32; d_Bv[2*64+m] = t48; d_Bv[3*64+m] = a;
    }
}

// -------- init: h_first + node mask --------
__global__ void init_kernel(const float* __restrict__ h0) {
    int node = blockIdx.x; int c = threadIdx.x; // 64 threads
    float v = (c < 32) ? h0[node*32 + c] : 0.f;
    d_hf[node*64 + c] = v;
    float s = (c < 32) ? v : 0.f;
    #pragma unroll
    for (int off = 16; off > 0; off >>= 1) s += __shfl_down_sync(0xffffffffu, s, off);
    if (c == 0) d_mask[node] = (s > 0.f) ? 1.f : 0.f;
}

// -------- edge MLP (16 -> 128 relu -> 128 relu) : the big GEMM --------
__global__ void __launch_bounds__(256) relu2_kernel(const float* __restrict__ e,
        const float* __restrict__ w0, const float* __restrict__ b0,
        const float* __restrict__ w1, const float* __restrict__ b1) {
    __shared__ float es[64*16];
    __shared__ float w0s[16*128];
    __shared__ float b0s[128];
    __shared__ float b1s[128];
    __shared__ float x1s[64*128];
    int t = threadIdx.x;
    int row0 = blockIdx.x * 64;
    for (int idx = t; idx < 1024; idx += 256) es[idx] = e[row0*16 + idx];
    for (int idx = t; idx < 2048; idx += 256) w0s[idx] = w0[idx];
    if (t < 128) { b0s[t] = b0[t]; b1s[t] = b1[t]; }
    __syncthreads();
    // layer 1: 16 -> 128
    {
        int c = t & 127, rh = t >> 7;
        for (int rr = 0; rr < 32; ++rr) {
            int r = rh*32 + rr;
            float acc = b0s[c];
            #pragma unroll
            for (int k = 0; k < 16; ++k) acc += es[r*16+k] * w0s[k*128+c];
            x1s[r*128+c] = fmaxf(acc, 0.f);
        }
    }
    __syncthreads();
    // layer 2: 128 -> 128, 8 rows x 4 cols per thread
    {
        int cg = t & 31, rg = t >> 5;
        float acc[8][4];
        #pragma unroll
        for (int rr = 0; rr < 8; ++rr) {
            #pragma unroll
            for (int q = 0; q < 4; ++q) acc[rr][q] = b1s[cg*4+q];
        }
        for (int k = 0; k < 128; ++k) {
            float4 w = *(const float4*)(w1 + k*128 + cg*4);
            #pragma unroll
            for (int rr = 0; rr < 8; ++rr) {
                float xv = x1s[(rg*8+rr)*128 + k];
                acc[rr][0] += xv*w.x; acc[rr][1] += xv*w.y;
                acc[rr][2] += xv*w.z; acc[rr][3] += xv*w.w;
            }
        }
        #pragma unroll
        for (int rr = 0; rr < 8; ++rr) {
            int r = rg*8+rr;
            float4 o;
            o.x = fmaxf(acc[rr][0], 0.f); o.y = fmaxf(acc[rr][1], 0.f);
            o.z = fmaxf(acc[rr][2], 0.f); o.w = fmaxf(acc[rr][3], 0.f);
            *(float4*)(d_r2 + (row0+r)*128 + cg*4) = o;
        }
    }
}

// -------- fused message-agg + GRU layer; 4 batches per CTA, one j --------
__global__ void __launch_bounds__(128) layer_kernel(int inbuf, int outbuf,
        const float* __restrict__ g,
        const float* __restrict__ wih, const float* __restrict__ whh,
        const float* __restrict__ bih, const float* __restrict__ bhh) {
    const float* h_in  = (inbuf  == 0) ? d_hf : ((inbuf  == 1) ? d_hA : d_hB);
    float*       h_out = (outbuf == 1) ? d_hA : d_hB;
    int j = blockIdx.x; int b0 = blockIdx.y * 4;
    int t = threadIdx.x;
    int k0 = (4*j)/3;
    int a64 = (64*j) % 48;            // in {0,16,32}
    int sel = (48 - a64)/16 - 1;      // split 48->2, 32->1, 16->0

    __shared__ float a_s[4][48][2];
    __shared__ float hold[4][64];
    __shared__ float Dsm[4][128];
    __shared__ float P1sm[4][128];
    __shared__ float part[2][4][64];
    __shared__ float aggs[4][64];
    __shared__ float Qs[4][2];
    __shared__ float ghs[3][4][64];

    // Phase A: gather g*h terms + own-node hidden
    for (int idx = t; idx < 384; idx += 128) {
        int bb = idx / 96; int r = idx % 96; int i = r >> 1; int s = r & 1;
        int bi = (b0+bb)*48 + i;
        float gv = g[bi*48 + j];
        a_s[bb][i][s] = gv * h_in[bi*64 + k0 + s];
    }
    for (int idx = t; idx < 256; idx += 128) {
        int bb = idx >> 6; int c = idx & 63;
        hold[bb][c] = h_in[((b0+bb)*48 + j)*64 + c];
    }
    __syncthreads();

    // Phase B: P_s[bb][c] = sum_i a[bb][i][s] * relu2[e',c]
    {
        int c = t;
        float P0[4] = {0,0,0,0}, P1[4] = {0,0,0,0};
        for (int i = 0; i < 48; ++i) {
            #pragma unroll
            for (int bb = 0; bb < 4; ++bb) {
                float r2v = d_r2[(((b0+bb)*48 + i)*48 + j)*128 + c];
                P0[bb] += a_s[bb][i][0]*r2v;
                P1[bb] += a_s[bb][i][1]*r2v;
            }
        }
        #pragma unroll
        for (int bb = 0; bb < 4; ++bb) { Dsm[bb][c] = P0[bb]-P1[bb]; P1sm[bb][c] = P1[bb]; }
        if (t < 8) {
            int bb = t >> 1, s = t & 1;
            float q = 0.f;
            for (int i = 0; i < 48; ++i) q += a_s[bb][i][s];
            Qs[bb][s] = q;
        }
    }
    __syncthreads();

    // Phase C: agg[m] = sum_c Ssel*(P0-P1) + S64*P1  (+ bias via Q)
    {
        int m = t & 63, half = t >> 6;
        const float* Ssel = d_S + sel*8192;
        const float* S64g = d_S + 3*8192;
        float acc[4] = {0,0,0,0};
        int cbeg = half*64;
        for (int c = cbeg; c < cbeg+64; ++c) {
            float wsel = Ssel[c*64+m];
            float w64  = S64g[c*64+m];
            #pragma unroll
            for (int bb = 0; bb < 4; ++bb)
                acc[bb] += wsel*Dsm[bb][c] + w64*P1sm[bb][c];
        }
        #pragma unroll
        for (int bb = 0; bb < 4; ++bb) part[half][bb][m] = acc[bb];
    }
    __syncthreads();
    if (t < 64) {
        int m = t;
        float bs = d_Bv[sel*64+m], b64 = d_Bv[3*64+m];
        #pragma unroll
        for (int bb = 0; bb < 4; ++bb)
            aggs[bb][m] = part[0][bb][m] + part[1][bb][m]
                        + bs*(Qs[bb][0]-Qs[bb][1]) + b64*Qs[bb][1];
    }
    __syncthreads();

    // Phase D: GRU (gate order r,z,n), half 0 = input gates, half 1 = hidden gates
    float gi[3][4];
    {
        int c = t & 63, half = t >> 6;
        const float* W = half ? whh : wih;
        #pragma unroll
        for (int gg = 0; gg < 3; ++gg)
            #pragma unroll
            for (int bb = 0; bb < 4; ++bb) gi[gg][bb] = 0.f;
        for (int k = 0; k < 64; ++k) {
            float w_r = W[(c)*64 + k];
            float w_z = W[(64+c)*64 + k];
            float w_n = W[(128+c)*64 + k];
            #pragma unroll
            for (int bb = 0; bb < 4; ++bb) {
                float x = half ? hold[bb][k] : aggs[bb][k];
                gi[0][bb] += w_r*x; gi[1][bb] += w_z*x; gi[2][bb] += w_n*x;
            }
        }
        if (half) {
            #pragma unroll
            for (int gg = 0; gg < 3; ++gg)
                #pragma unroll
                for (int bb = 0; bb < 4; ++bb)
                    ghs[gg][bb][c] = gi[gg][bb] + bhh[gg*64+c];
        }
    }
    __syncthreads();
    if (t < 64) {
        int c = t;
        #pragma unroll
        for (int bb = 0; bb < 4; ++bb) {
            float r = 1.f/(1.f+expf(-(gi[0][bb] + bih[c]      + ghs[0][bb][c])));
            float z = 1.f/(1.f+expf(-(gi[1][bb] + bih[64+c]   + ghs[1][bb][c])));
            float n = tanhf(gi[2][bb] + bih[128+c] + r*ghs[2][bb][c]);
            float hn = (1.f-z)*n + z*hold[bb][c];
            int node = (b0+bb)*48 + j;
            h_out[node*64 + c] = d_mask[node]*hn;
        }
    }
}

// -------- readout: Net0(cat[h0,hT]) * Net1(hT), masked, per-node --------
__global__ void __launch_bounds__(128) readout_kernel(
   const float* __restrict__ r0w0, const float* __restrict__ r0b0,
   const float* __restrict__ r0w1, const float* __restrict__ r0b1,
   const float* __restrict__ r0w2, const float* __restrict__ r0b2,
   const float* __restrict__ r1w0, const float* __restrict__ r1b0,
   const float* __restrict__ r1w1, const float* __restrict__ r1b1,
   const float* __restrict__ r1w2, const float* __restrict__ r1b2) {
    __shared__ float xin[8][128];
    __shared__ float bufA[8][128];
    __shared__ float bufB[8][128];
    int t = threadIdx.x;
    int n0 = blockIdx.x * 8;
    for (int idx = t; idx < 1024; idx += 128) {
        int r = idx >> 7, c = idx & 127;
        int node = n0 + r;
        xin[r][c] = (c < 64) ? d_hf[node*64 + c] : d_hA[node*64 + (c-64)];
    }
    __syncthreads();
    int c = t;
    float acc[8];
    // Net0 L1 (128 -> 128, relu)
    #pragma unroll
    for (int r = 0; r < 8; ++r) acc[r] = r0b0[c];
    for (int k = 0; k < 128; ++k) { float w = r0w0[k*128+c];
        #pragma unroll
        for (int r = 0; r < 8; ++r) acc[r] += xin[r][k]*w; }
    #pragma unroll
    for (int r = 0; r < 8; ++r) bufA[r][c] = fmaxf(acc[r], 0.f);
    __syncthreads();
    // Net0 L2
    #pragma unroll
    for (int r = 0; r < 8; ++r) acc[r] = r0b1[c];
    for (int k = 0; k < 128; ++k) { float w = r0w1[k*128+c];
        #pragma unroll
        for (int r = 0; r < 8; ++r) acc[r] += bufA[r][k]*w; }
    #pragma unroll
    for (int r = 0; r < 8; ++r) bufB[r][c] = fmaxf(acc[r], 0.f);
    __syncthreads();
    // Net0 L3 (linear) -> regs
    float out0[8];
    #pragma unroll
    for (int r = 0; r < 8; ++r) out0[r] = r0b2[c];
    for (int k = 0; k < 128; ++k) { float w = r0w2[k*128+c];
        #pragma unroll
        for (int r = 0; r < 8; ++r) out0[r] += bufB[r][k]*w; }
    __syncthreads();
    // Net1 L1 (64 -> 128, relu) from hT half of xin
    #pragma unroll
    for (int r = 0; r < 8; ++r) acc[r] = r1b0[c];
    for (int k = 0; k < 64; ++k) { float w = r1w0[k*128+c];
        #pragma unroll
        for (int r = 0; r < 8; ++r) acc[r] += xin[r][64+k]*w; }
    #pragma unroll
    for (int r = 0; r < 8; ++r) bufA[r][c] = fmaxf(acc[r], 0.f);
    __syncthreads();
    // Net1 L2
    #pragma unroll
    for (int r = 0; r < 8; ++r) acc[r] = r1b1[c];
    for (int k = 0; k < 128; ++k) { float w = r1w1[k*128+c];
        #pragma unroll
        for (int r = 0; r < 8; ++r) acc[r] += bufA[r][k]*w; }
    #pragma unroll
    for (int r = 0; r < 8; ++r) bufB[r][c] = fmaxf(acc[r], 0.f);
    __syncthreads();
    // Net1 L3 (linear), multiply, mask, store
    #pragma unroll
    for (int r = 0; r < 8; ++r) acc[r] = r1b2[c];
    for (int k = 0; k < 128; ++k) { float w = r1w2[k*128+c];
        #pragma unroll
        for (int r = 0; r < 8; ++r) acc[r] += bufB[r][k]*w; }
    #pragma unroll
    for (int r = 0; r < 8; ++r) {
        int node = n0 + r;
        d_tmp[node*128 + c] = d_mask[node]*out0[r]*acc[r];
    }
}

// -------- final node-sum + sigmoid --------
__global__ void reduce_kernel(float* __restrict__ out) {
    int b = blockIdx.x; int t = threadIdx.x;  // 128 threads
    float s = 0.f;
    #pragma unroll 4
    for (int j = 0; j < 48; ++j) s += d_tmp[(b*48+j)*128 + t];
    out[b*128+t] = 1.f/(1.f+expf(-s));
}

extern "C" void kernel_launch(void* const* d_in, const int* in_sizes, int n_in,
                              void* d_out, int out_size) {
    const float* g       = (const float*)d_in[0];
    const float* h0      = (const float*)d_in[1];
    const float* e       = (const float*)d_in[2];
    const float* msg_w0  = (const float*)d_in[3];
    const float* msg_b0  = (const float*)d_in[4];
    const float* msg_w1  = (const float*)d_in[5];
    const float* msg_b1  = (const float*)d_in[6];
    const float* msg_w2  = (const float*)d_in[7];
    const float* msg_b2  = (const float*)d_in[8];
    const float* gru_wih = (const float*)d_in[9];
    const float* gru_whh = (const float*)d_in[10];
    const float* gru_bih = (const float*)d_in[11];
    const float* gru_bhh = (const float*)d_in[12];
    const float* r0_w0   = (const float*)d_in[13];
    const float* r0_b0   = (const float*)d_in[14];
    const float* r0_w1   = (const float*)d_in[15];
    const float* r0_b1   = (const float*)d_in[16];
    const float* r0_w2   = (const float*)d_in[17];
    const float* r0_b2   = (const float*)d_in[18];
    const float* r1_w0   = (const float*)d_in[19];
    const float* r1_b0   = (const float*)d_in[20];
    const float* r1_w1   = (const float*)d_in[21];
    const float* r1_b1   = (const float*)d_in[22];
    const float* r1_w2   = (const float*)d_in[23];
    const float* r1_b2   = (const float*)d_in[24];
    float* out = (float*)d_out;

    prep_kernel<<<128, 64>>>(msg_w2, msg_b2);
    init_kernel<<<NNODE, 64>>>(h0);
    relu2_kernel<<<NE/64, 256>>>(e, msg_w0, msg_b0, msg_w1, msg_b1);
    // L1: hf -> hA ; L2: hA -> hB ; L3: hB -> hA
    layer_kernel<<<dim3(48, 4), 128>>>(0, 1, g, gru_wih, gru_whh, gru_bih, gru_bhh);
    layer_kernel<<<dim3(48, 4), 128>>>(1, 2, g, gru_wih, gru_whh, gru_bih, gru_bhh);
    layer_kernel<<<dim3(48, 4), 128>>>(2, 1, g, gru_wih, gru_whh, gru_bih, gru_bhh);
    readout_kernel<<<NNODE/8, 128>>>(r0_w0, r0_b0, r0_w1, r0_b1, r0_w2, r0_b2,
                                     r1_w0, r1_b0, r1_w1, r1_b1, r1_w2, r1_b2);
    reduce_kernel<<<NB, 128>>>(out);
}

// round 2
// speedup vs baseline: 1.6258x; 1.6258x over previous
#include <cuda_runtime.h>
#include <math.h>

#define NB 16
#define NN 48
#define HID 64
#define MSG 64
#define EDGE 16
#define NL 128
#define TGT 128
#define NE (NB*NN*NN)    // 36864 edges
#define NNODE (NB*NN)    // 768 nodes

// -------- device scratch (static; no allocation) --------
__device__ float2 d_SP[3*NL*MSG];   // [sel][c][m] -> (S_cut, S64 - S_cut)
__device__ float2 d_Bp[3*MSG];      // [sel][m]    -> (B_cut, B64 - B_cut)
__device__ float d_wiht[HID*3*HID]; // transposed gru_wih: [k][gate][c]
__device__ float d_whht[HID*3*HID]; // transposed gru_whh: [k][gate][c]
__device__ float d_r2[NE*NL];       // relu2 activations per edge [e'][c]
__device__ float d_hf[NNODE*HID];   // h_first
__device__ float d_hA[NNODE*HID];
__device__ float d_hB[NNODE*HID];
__device__ float d_mask[NNODE];
__device__ float d_tmp[NNODE*TGT];

// -------- prep: prefix-sum weight tables (combined float2 form) --------
__global__ void prep_kernel(const float* __restrict__ w2, const float* __restrict__ b2) {
    int c = blockIdx.x;   // 0..127
    int m = threadIdx.x;  // 0..63
    const float* p = w2 + c*4096 + m*64;
    float acc = 0.f, s16 = 0.f, s32 = 0.f, s48 = 0.f;
    #pragma unroll
    for (int h = 0; h < 64; ++h) {
        acc += p[h];
        if (h == 15) s16 = acc;
        if (h == 31) s32 = acc;
        if (h == 47) s48 = acc;
    }
    d_SP[0*8192 + c*64 + m] = make_float2(s16, acc - s16);
    d_SP[1*8192 + c*64 + m] = make_float2(s32, acc - s32);
    d_SP[2*8192 + c*64 + m] = make_float2(s48, acc - s48);
    if (c == 0) {
        const float* q = b2 + m*64;
        float a = 0.f, t16 = 0.f, t32 = 0.f, t48 = 0.f;
        for (int h = 0; h < 64; ++h) {
            a += q[h];
            if (h == 15) t16 = a;
            if (h == 31) t32 = a;
            if (h == 47) t48 = a;
        }
        d_Bp[0*64+m] = make_float2(t16, a - t16);
        d_Bp[1*64+m] = make_float2(t32, a - t32);
        d_Bp[2*64+m] = make_float2(t48, a - t48);
    }
}

// -------- prep: transpose GRU weights to [k][gate*64+c] --------
__global__ void prep_gru_kernel(const float* __restrict__ wih, const float* __restrict__ whh) {
    int k = blockIdx.x;       // 0..63
    int t = threadIdx.x;      // 0..191 = gate*64+c
    d_wiht[k*192 + t] = wih[t*64 + k];
    d_whht[k*192 + t] = whh[t*64 + k];
}

// -------- init: h_first + node mask --------
__global__ void init_kernel(const float* __restrict__ h0) {
    int node = blockIdx.x; int c = threadIdx.x; // 64 threads
    float v = (c < 32) ? h0[node*32 + c] : 0.f;
    d_hf[node*64 + c] = v;
    float s = (c < 32) ? v : 0.f;
    #pragma unroll
    for (int off = 16; off > 0; off >>= 1) s += __shfl_down_sync(0xffffffffu, s, off);
    if (c == 0) d_mask[node] = (s > 0.f) ? 1.f : 0.f;
}

// -------- edge MLP (16 -> 128 relu -> 128 relu) : the big GEMM --------
__global__ void __launch_bounds__(256) relu2_kernel(const float* __restrict__ e,
        const float* __restrict__ w0, const float* __restrict__ b0,
        const float* __restrict__ w1, const float* __restrict__ b1) {
    __shared__ float es[64*16];
    __shared__ float w0s[16*128];
    __shared__ float b0s[128];
    __shared__ float b1s[128];
    __shared__ float x1s[64*128];
    int t = threadIdx.x;
    int row0 = blockIdx.x * 64;
    for (int idx = t; idx < 1024; idx += 256) es[idx] = e[row0*16 + idx];
    for (int idx = t; idx < 2048; idx += 256) w0s[idx] = w0[idx];
    if (t < 128) { b0s[t] = b0[t]; b1s[t] = b1[t]; }
    __syncthreads();
    // layer 1: 16 -> 128
    {
        int c = t & 127, rh = t >> 7;
        for (int rr = 0; rr < 32; ++rr) {
            int r = rh*32 + rr;
            float acc = b0s[c];
            #pragma unroll
            for (int k = 0; k < 16; ++k) acc += es[r*16+k] * w0s[k*128+c];
            x1s[r*128+c] = fmaxf(acc, 0.f);
        }
    }
    __syncthreads();
    // layer 2: 128 -> 128, 8 rows x 4 cols per thread
    {
        int cg = t & 31, rg = t >> 5;
        float acc[8][4];
        #pragma unroll
        for (int rr = 0; rr < 8; ++rr) {
            #pragma unroll
            for (int q = 0; q < 4; ++q) acc[rr][q] = b1s[cg*4+q];
        }
        for (int k = 0; k < 128; ++k) {
            float4 w = *(const float4*)(w1 + k*128 + cg*4);
            #pragma unroll
            for (int rr = 0; rr < 8; ++rr) {
                float xv = x1s[(rg*8+rr)*128 + k];
                acc[rr][0] += xv*w.x; acc[rr][1] += xv*w.y;
                acc[rr][2] += xv*w.z; acc[rr][3] += xv*w.w;
            }
        }
        #pragma unroll
        for (int rr = 0; rr < 8; ++rr) {
            int r = rg*8+rr;
            float4 o;
            o.x = fmaxf(acc[rr][0], 0.f); o.y = fmaxf(acc[rr][1], 0.f);
            o.z = fmaxf(acc[rr][2], 0.f); o.w = fmaxf(acc[rr][3], 0.f);
            *(float4*)(d_r2 + (row0+r)*128 + cg*4) = o;
        }
    }
}

// -------- fused message-agg + GRU layer; one (b, j) per CTA --------
__global__ void __launch_bounds__(128) layer_kernel(int inbuf, int outbuf,
        const float* __restrict__ g,
        const float* __restrict__ bih, const float* __restrict__ bhh) {
    const float* h_in  = (inbuf  == 0) ? d_hf : ((inbuf  == 1) ? d_hA : d_hB);
    float*       h_out = (outbuf == 1) ? d_hA : d_hB;
    int j = blockIdx.x; int b = blockIdx.y;
    int t = threadIdx.x;
    int k0 = (4*j)/3;
    int a64 = (64*j) % 48;            // in {0,16,32}
    int sel = (48 - a64)/16 - 1;      // 48->2, 32->1, 16->0

    __shared__ float a_s[48][2];
    __shared__ float hold[64];
    __shared__ float P0sm[128];
    __shared__ float P1sm[128];
    __shared__ float part[2][64];
    __shared__ float aggs[64];
    __shared__ float Qs[2];
    __shared__ float ghs[3][64];

    // Phase A: gather g*h terms + own-node hidden
    if (t < 96) {
        int i = t >> 1, s = t & 1;
        int bi = b*48 + i;
        float gv = __ldg(&g[bi*48 + j]);
        a_s[i][s] = gv * h_in[bi*64 + k0 + s];
    }
    if (t >= 64) {
        int c = t - 64;
        hold[c] = h_in[(b*48 + j)*64 + c];
    }
    __syncthreads();

    // Phase B: P_s[c] = sum_i a[i][s] * relu2[e',c]
    {
        int c = t;
        float P0 = 0.f, P1 = 0.f;
        const float* r2p = d_r2 + (b*2304 + j)*128 + c;  // stride 6144 over i
        #pragma unroll 8
        for (int i = 0; i < 48; ++i) {
            float r2v = __ldg(r2p + i*6144);
            P0 += a_s[i][0]*r2v;
            P1 += a_s[i][1]*r2v;
        }
        P0sm[c] = P0; P1sm[c] = P1;
        if (t < 2) {
            float q = 0.f;
            #pragma unroll
            for (int i = 0; i < 48; ++i) q += a_s[i][t];
            Qs[t] = q;
        }
    }
    __syncthreads();

    // Phase C: agg[m] = sum_c SP.x*P0 + SP.y*P1   (+ bias via Q)
    {
        int m = t & 63, half = t >> 6;
        const float2* SP = d_SP + sel*8192;
        float acc = 0.f;
        int cbeg = half*64;
        #pragma unroll 4
        for (int c = cbeg; c < cbeg+64; ++c) {
            float2 w = __ldg(&SP[c*64+m]);
            acc += w.x*P0sm[c] + w.y*P1sm[c];
        }
        part[half][m] = acc;
    }
    __syncthreads();
    if (t < 64) {
        int m = t;
        float2 bp = d_Bp[sel*64+m];
        aggs[m] = part[0][m] + part[1][m] + bp.x*Qs[0] + bp.y*Qs[1];
    }
    __syncthreads();

    // Phase D: GRU (gate order r,z,n); half 0 = input gates, half 1 = hidden gates
    float g0 = 0.f, g1 = 0.f, g2 = 0.f;
    {
        int c = t & 63, half = t >> 6;
        const float* Wt = half ? d_whht : d_wiht;
        #pragma unroll 4
        for (int k = 0; k < 64; ++k) {
            float x = half ? hold[k] : aggs[k];
            g0 += Wt[k*192 + c]       * x;
            g1 += Wt[k*192 + 64 + c]  * x;
            g2 += Wt[k*192 + 128 + c] * x;
        }
        if (half) {
            ghs[0][c] = g0 + bhh[c];
            ghs[1][c] = g1 + bhh[64+c];
            ghs[2][c] = g2 + bhh[128+c];
        }
    }
    __syncthreads();
    if (t < 64) {
        int c = t;
        float r = 1.f/(1.f+expf(-(g0 + bih[c]      + ghs[0][c])));
        float z = 1.f/(1.f+expf(-(g1 + bih[64+c]   + ghs[1][c])));
        float n = tanhf(g2 + bih[128+c] + r*ghs[2][c]);
        float hn = (1.f-z)*n + z*hold[c];
        int node = b*48 + j;
        h_out[node*64 + c] = d_mask[node]*hn;
    }
}

// -------- readout: Net0(cat[h0,hT]) * Net1(hT), masked, per-node --------
__global__ void __launch_bounds__(128) readout_kernel(
   const float* __restrict__ r0w0, const float* __restrict__ r0b0,
   const float* __restrict__ r0w1, const float* __restrict__ r0b1,
   const float* __restrict__ r0w2, const float* __restrict__ r0b2,
   const float* __restrict__ r1w0, const float* __restrict__ r1b0,
   const float* __restrict__ r1w1, const float* __restrict__ r1b1,
   const float* __restrict__ r1w2, const float* __restrict__ r1b2) {
    __shared__ float xin[8][128];
    __shared__ float bufA[8][128];
    __shared__ float bufB[8][128];
    int t = threadIdx.x;
    int n0 = blockIdx.x * 8;
    for (int idx = t; idx < 1024; idx += 128) {
        int r = idx >> 7, c = idx & 127;
        int node = n0 + r;
        xin[r][c] = (c < 64) ? d_hf[node*64 + c] : d_hA[node*64 + (c-64)];
    }
    __syncthreads();
    int c = t;
    float acc[8];
    // Net0 L1 (128 -> 128, relu)
    #pragma unroll
    for (int r = 0; r < 8; ++r) acc[r] = r0b0[c];
    for (int k = 0; k < 128; ++k) { float w = r0w0[k*128+c];
        #pragma unroll
        for (int r = 0; r < 8; ++r) acc[r] += xin[r][k]*w; }
    #pragma unroll
    for (int r = 0; r < 8; ++r) bufA[r][c] = fmaxf(acc[r], 0.f);
    __syncthreads();
    // Net0 L2
    #pragma unroll
    for (int r = 0; r < 8; ++r) acc[r] = r0b1[c];
    for (int k = 0; k < 128; ++k) { float w = r0w1[k*128+c];
        #pragma unroll
        for (int r = 0; r < 8; ++r) acc[r] += bufA[r][k]*w; }
    #pragma unroll
    for (int r = 0; r < 8; ++r) bufB[r][c] = fmaxf(acc[r], 0.f);
    __syncthreads();
    // Net0 L3 (linear) -> regs
    float out0[8];
    #pragma unroll
    for (int r = 0; r < 8; ++r) out0[r] = r0b2[c];
    for (int k = 0; k < 128; ++k) { float w = r0w2[k*128+c];
        #pragma unroll
        for (int r = 0; r < 8; ++r) out0[r] += bufB[r][k]*w; }
    __syncthreads();
    // Net1 L1 (64 -> 128, relu) from hT half of xin
    #pragma unroll
    for (int r = 0; r < 8; ++r) acc[r] = r1b0[c];
    for (int k = 0; k < 64; ++k) { float w = r1w0[k*128+c];
        #pragma unroll
        for (int r = 0; r < 8; ++r) acc[r] += xin[r][64+k]*w; }
    #pragma unroll
    for (int r = 0; r < 8; ++r) bufA[r][c] = fmaxf(acc[r], 0.f);
    __syncthreads();
    // Net1 L2
    #pragma unroll
    for (int r = 0; r < 8; ++r) acc[r] = r1b1[c];
    for (int k = 0; k < 128; ++k) { float w = r1w1[k*128+c];
        #pragma unroll
        for (int r = 0; r < 8; ++r) acc[r] += bufA[r][k]*w; }
    #pragma unroll
    for (int r = 0; r < 8; ++r) bufB[r][c] = fmaxf(acc[r], 0.f);
    __syncthreads();
    // Net1 L3 (linear), multiply, mask, store
    #pragma unroll
    for (int r = 0; r < 8; ++r) acc[r] = r1b2[c];
    for (int k = 0; k < 128; ++k) { float w = r1w2[k*128+c];
        #pragma unroll
        for (int r = 0; r < 8; ++r) acc[r] += bufB[r][k]*w; }
    #pragma unroll
    for (int r = 0; r < 8; ++r) {
        int node = n0 + r;
        d_tmp[node*128 + c] = d_mask[node]*out0[r]*acc[r];
    }
}

// -------- final node-sum + sigmoid --------
__global__ void reduce_kernel(float* __restrict__ out) {
    int b = blockIdx.x; int t = threadIdx.x;  // 128 threads
    float s = 0.f;
    #pragma unroll 4
    for (int j = 0; j < 48; ++j) s += d_tmp[(b*48+j)*128 + t];
    out[b*128+t] = 1.f/(1.f+expf(-s));
}

extern "C" void kernel_launch(void* const* d_in, const int* in_sizes, int n_in,
                              void* d_out, int out_size) {
    const float* g       = (const float*)d_in[0];
    const float* h0      = (const float*)d_in[1];
    const float* e       = (const float*)d_in[2];
    const float* msg_w0  = (const float*)d_in[3];
    const float* msg_b0  = (const float*)d_in[4];
    const float* msg_w1  = (const float*)d_in[5];
    const float* msg_b1  = (const float*)d_in[6];
    const float* msg_w2  = (const float*)d_in[7];
    const float* msg_b2  = (const float*)d_in[8];
    const float* gru_wih = (const float*)d_in[9];
    const float* gru_whh = (const float*)d_in[10];
    const float* gru_bih = (const float*)d_in[11];
    const float* gru_bhh = (const float*)d_in[12];
    const float* r0_w0   = (const float*)d_in[13];
    const float* r0_b0   = (const float*)d_in[14];
    const float* r0_w1   = (const float*)d_in[15];
    const float* r0_b1   = (const float*)d_in[16];
    const float* r0_w2   = (const float*)d_in[17];
    const float* r0_b2   = (const float*)d_in[18];
    const float* r1_w0   = (const float*)d_in[19];
    const float* r1_b0   = (const float*)d_in[20];
    const float* r1_w1   = (const float*)d_in[21];
    const float* r1_b1   = (const float*)d_in[22];
    const float* r1_w2   = (const float*)d_in[23];
    const float* r1_b2   = (const float*)d_in[24];
    float* out = (float*)d_out;

    prep_kernel<<<128, 64>>>(msg_w2, msg_b2);
    prep_gru_kernel<<<64, 192>>>(gru_wih, gru_whh);
    init_kernel<<<NNODE, 64>>>(h0);
    relu2_kernel<<<NE/64, 256>>>(e, msg_w0, msg_b0, msg_w1, msg_b1);
    // L1: hf -> hA ; L2: hA -> hB ; L3: hB -> hA
    layer_kernel<<<dim3(48, 16), 128>>>(0, 1, g, gru_bih, gru_bhh);
    layer_kernel<<<dim3(48, 16), 128>>>(1, 2, g, gru_bih, gru_bhh);
    layer_kernel<<<dim3(48, 16), 128>>>(2, 1, g, gru_bih, gru_bhh);
    readout_kernel<<<NNODE/8, 128>>>(r0_w0, r0_b0, r0_w1, r0_b1, r0_w2, r0_b2,
                                     r1_w0, r1_b0, r1_w1, r1_b1, r1_w2, r1_b2);
    reduce_kernel<<<NB, 128>>>(out);
}